// round 4
// baseline (speedup 1.0000x reference)
#include <cuda_runtime.h>

#define BB   256
#define TT   2048
#define INW  29
#define HH   64
#define GG   192   // 3*H
#define OUTW 11

// Scratch (no cudaMalloc allowed).
__device__ float g_gx[(size_t)2 * BB * TT * GG];       // [dir][b][t][g] (natural t)
__device__ float g_out0[(size_t)BB * TT * 2 * HH];      // [b][t][128]
__device__ float g_hT[2 * BB * HH];                     // [dir][b][h]

typedef unsigned long long u64;

__device__ __forceinline__ u64 pk2(float lo, float hi) {
    u64 r; asm("mov.b64 %0,{%1,%2};" : "=l"(r) : "f"(lo), "f"(hi)); return r;
}
__device__ __forceinline__ void upk2(u64 v, float& lo, float& hi) {
    asm("mov.b64 {%0,%1},%2;" : "=f"(lo), "=f"(hi) : "l"(v));
}
// Packed fp32x2 FMA (Blackwell FFMA2) — 2x FFMA throughput vs 3-reg FFMA.
__device__ __forceinline__ u64 fma2(u64 a, u64 b, u64 c) {
    u64 d; asm("fma.rn.f32x2 %0,%1,%2,%3;" : "=l"(d) : "l"(a), "l"(b), "l"(c)); return d;
}
__device__ __forceinline__ u64 add2(u64 a, u64 b) {
    u64 d; asm("add.rn.f32x2 %0,%1,%2;" : "=l"(d) : "l"(a), "l"(b)); return d;
}
__device__ __forceinline__ float hadd2(u64 v) {
    float lo, hi; upk2(v, lo, hi); return lo + hi;
}

__device__ __forceinline__ float sigm(float x)  { return __fdividef(1.f, 1.f + __expf(-x)); }
__device__ __forceinline__ float tanh_(float x) { return __fdividef(2.f, 1.f + __expf(-2.f * x)) - 1.f; }

// ---------------------------------------------------------------------------
// Layer-0 input GEMM: gx[dir][b][t][g] = bih[g] + sum_k Wih[g][k]*x[b][t][k]
// Natural time order for both dirs (recurrence walks backward for dir=1).
// ---------------------------------------------------------------------------
__global__ __launch_bounds__(192) void gx0_kernel(
    const float* __restrict__ x,
    const float* __restrict__ Wf, const float* __restrict__ bf,
    const float* __restrict__ Wb, const float* __restrict__ bb)
{
    int dir = blockIdx.z, b = blockIdx.y, t0 = blockIdx.x * 64;
    const float* W  = dir ? Wb : Wf;
    const float* bi = dir ? bb : bf;
    int j = threadIdx.x;

    u64 w2[INW];
#pragma unroll
    for (int k = 0; k < INW; k++) { float w = W[j * INW + k]; w2[k] = pk2(w, w); }
    float bias = bi[j];

    __shared__ __align__(16) float2 xs[INW][32];   // [k][t-pair], 64 timesteps
    for (int idx = j; idx < 64 * INW; idx += 192) {
        int tt = idx / INW, k = idx - tt * INW;
        float v = x[((size_t)b * TT + t0 + tt) * INW + k];
        ((float*)&xs[k][tt >> 1])[tt & 1] = v;
    }
    __syncthreads();

    const ulonglong2* xsq = (const ulonglong2*)xs;  // [k][16] pairs-of-pairs
    float* gxp = g_gx + ((size_t)(dir * BB + b) * TT + t0) * GG + j;
#pragma unroll 1
    for (int p2 = 0; p2 < 16; p2++) {
        u64 a0 = 0ull, a1 = 0ull;
#pragma unroll
        for (int k = 0; k < INW; k++) {
            ulonglong2 v = xsq[k * 16 + p2];
            a0 = fma2(w2[k], v.x, a0);
            a1 = fma2(w2[k], v.y, a1);
        }
        float q0, q1, q2, q3;
        upk2(a0, q0, q1); upk2(a1, q2, q3);
        gxp[(size_t)(4 * p2)     * GG] = q0 + bias;
        gxp[(size_t)(4 * p2 + 1) * GG] = q1 + bias;
        gxp[(size_t)(4 * p2 + 2) * GG] = q2 + bias;
        gxp[(size_t)(4 * p2 + 3) * GG] = q3 + bias;
    }
}

// ---------------------------------------------------------------------------
// Layer-1 input GEMM (K=128). K split across lane halves of the same warp:
// lanes l / l^16 hold the two K-halves of gate j; combine via shfl_xor.
// ---------------------------------------------------------------------------
__global__ __launch_bounds__(384) void gx1_kernel(
    const float* __restrict__ Wf, const float* __restrict__ bf,
    const float* __restrict__ Wb, const float* __restrict__ bb)
{
    int dir = blockIdx.z, b = blockIdx.y, t0 = blockIdx.x * 64;
    const float* W  = dir ? Wb : Wf;
    const float* bi = dir ? bb : bf;
    int tid = threadIdx.x;
    int w = tid >> 5, l = tid & 31;
    int j  = (w << 4) | (l & 15);
    int kh = l >> 4;

    u64 w2[32];                      // pairwise-k packed K-half
#pragma unroll
    for (int i = 0; i < 32; i++)
        w2[i] = pk2(W[j * 128 + kh * 64 + 2 * i], W[j * 128 + kh * 64 + 2 * i + 1]);
    float bias = bi[j];

    __shared__ __align__(16) float ins[64][128];   // [t][k], 32 KB
    {
        const float4* src = (const float4*)(g_out0 + ((size_t)b * TT + t0) * 128);
        float4* dst = (float4*)ins;
        for (int idx = tid; idx < 64 * 32; idx += 384) dst[idx] = src[idx];
    }
    __syncthreads();

    float* gxp = g_gx + ((size_t)(dir * BB + b) * TT + t0) * GG + j;
#pragma unroll 1
    for (int t = 0; t < 64; t++) {
        const ulonglong2* row = (const ulonglong2*)&ins[t][kh * 64];
        u64 a0 = 0ull, a1 = 0ull;
#pragma unroll
        for (int i = 0; i < 16; i++) {
            ulonglong2 v = row[i];
            a0 = fma2(w2[2 * i],     v.x, a0);
            a1 = fma2(w2[2 * i + 1], v.y, a1);
        }
        float s = hadd2(add2(a0, a1));
        s += __shfl_xor_sync(0xffffffffu, s, 16);
        if (kh == 0) gxp[(size_t)t * GG] = s + bias;
    }
}

// ---------------------------------------------------------------------------
// GRU recurrence, K-split variant: one CTA per (dir, batch-pair), 384 threads,
// 2 CTAs/SM (24 warps). Thread = (gate j, K-half kh): 16 weight-pair regs,
// 32 fma2/step over both batches (chain depth 8), shfl_xor(16) K-combine.
// Epilogue spread across 128 threads (one batch each). gx prefetched 4 deep,
// 1 LDG/thread/step (384 threads = 192 gates x 2 seqs exactly).
// ---------------------------------------------------------------------------
__global__ __launch_bounds__(384, 2) void recur_kernel(
    const float* __restrict__ Whf, const float* __restrict__ bhf,
    const float* __restrict__ Whb, const float* __restrict__ bhb,
    int layer)
{
    int pair = blockIdx.x, dir = blockIdx.y;
    int b0 = 2 * pair, b1 = b0 + 1;
    const float* W  = dir ? Whb : Whf;
    const float* bh = dir ? bhb : bhf;
    int tid = threadIdx.x;
    int w = tid >> 5, l = tid & 31;
    int j  = (w << 4) | (l & 15);    // gate row 0..191
    int kh = l >> 4;                  // K-half: h[kh*32 .. kh*32+31]

    u64 w2[16];
#pragma unroll
    for (int i = 0; i < 16; i++)
        w2[i] = pk2(W[j * HH + kh * 32 + 2 * i], W[j * HH + kh * 32 + 2 * i + 1]);
    float bj = (kh == 0) ? bh[j] : 0.f;
    bool is_n = (j >= 2 * HH);

    __shared__ __align__(16) float hA[HH], hB[HH];
    __shared__ float2 s2[GG];          // combined gate pre-acts, lanes=(b0,b1)
    __shared__ float gnA[HH], gnB[HH]; // gx n-part per batch
    if (tid < HH) { hA[tid] = 0.f; hB[tid] = 0.f; }

    // gx prefetch: this thread covers gate j of seq (kh ? b1 : b0), 4 deep.
    long stp = dir ? -(long)GG : (long)GG;
    const float* gp = g_gx
        + ((size_t)(dir * BB + (kh ? b1 : b0)) * TT + (dir ? TT - 1 : 0)) * GG + j;
    float f0 = gp[0], f1 = gp[stp], f2 = gp[2 * stp], f3 = gp[3 * stp];
    gp += 3 * stp;
    __syncthreads();

    const ulonglong2* hAq = (const ulonglong2*)(hA + kh * 32);
    const ulonglong2* hBq = (const ulonglong2*)(hB + kh * 32);
    int hj = j & 63;

    for (int t = 0; t < TT; t++) {
        float fn = 0.f;
        if (t + 4 < TT) { gp += stp; fn = *gp; }

        u64 aA0 = 0ull, aA1 = 0ull, aB0 = 0ull, aB1 = 0ull;
#pragma unroll
        for (int i = 0; i < 8; i++) {
            ulonglong2 va = hAq[i];
            ulonglong2 vb = hBq[i];
            aA0 = fma2(w2[2 * i],     va.x, aA0);
            aA1 = fma2(w2[2 * i + 1], va.y, aA1);
            aB0 = fma2(w2[2 * i],     vb.x, aB0);
            aB1 = fma2(w2[2 * i + 1], vb.y, aB1);
        }
        float sA = hadd2(add2(aA0, aA1)) + bj;
        float sB = hadd2(add2(aB0, aB1)) + bj;

        // r,z gates: fold gx of own batch into the pre-shuffle partial
        if (!is_n) { if (kh == 0) sA += f0; else sB += f0; }
        sA += __shfl_xor_sync(0xffffffffu, sA, 16);
        sB += __shfl_xor_sync(0xffffffffu, sB, 16);
        if (kh == 0) s2[j] = make_float2(sA, sB);
        if (is_n)    { if (kh == 0) gnA[hj] = f0; else gnB[hj] = f0; }
        __syncthreads();

        // Epilogue: 128 workers, one (batch, gate) h-update each.
        if (j < 2 * HH && kh == 0) {
            if (j < HH) {           // batch A, gate j
                float sr = s2[j].x, sz = s2[HH + j].x, hn = s2[2 * HH + j].x;
                float xn = gnA[j], hp = hA[j];
                float r = sigm(sr), z = sigm(sz);
                float n = tanh_(fmaf(r, hn, xn));
                float hN = fmaf(z, hp - n, n);
                hA[j] = hN;
                if (layer == 0) {
                    int tout = dir ? (TT - 1 - t) : t;
                    g_out0[((size_t)b0 * TT + tout) * (2 * HH) + dir * HH + j] = hN;
                }
            } else {                // batch B, gate hj
                float sr = s2[hj].y, sz = s2[HH + hj].y, hn = s2[2 * HH + hj].y;
                float xn = gnB[hj], hp = hB[hj];
                float r = sigm(sr), z = sigm(sz);
                float n = tanh_(fmaf(r, hn, xn));
                float hN = fmaf(z, hp - n, n);
                hB[hj] = hN;
                if (layer == 0) {
                    int tout = dir ? (TT - 1 - t) : t;
                    g_out0[((size_t)b1 * TT + tout) * (2 * HH) + dir * HH + hj] = hN;
                }
            }
        }
        __syncthreads();
        f0 = f1; f1 = f2; f2 = f3; f3 = fn;
    }

    if (layer == 1 && j < 2 * HH && kh == 0) {
        if (j < HH) g_hT[(dir * BB + b0) * HH + j]  = hA[j];
        else        g_hT[(dir * BB + b1) * HH + hj] = hB[hj];
    }
}

// ---------------------------------------------------------------------------
// Head: LayerNorm(concat(hTf, hTb)) -> ReLU(W1) -> W2. One block per batch.
// ---------------------------------------------------------------------------
__global__ __launch_bounds__(128) void head_kernel(
    const float* __restrict__ ln_g, const float* __restrict__ ln_b,
    const float* __restrict__ W1,  const float* __restrict__ b1,
    const float* __restrict__ W2,  const float* __restrict__ b2,
    float* __restrict__ out)
{
    int b = blockIdx.x, i = threadIdx.x;
    __shared__ float y[128];
    __shared__ float hh[64];
    __shared__ float red[16];

    float e = (i < 64) ? g_hT[(0 * BB + b) * HH + i]
                       : g_hT[(1 * BB + b) * HH + (i - 64)];
    float s = e, q = e * e;
#pragma unroll
    for (int o = 16; o > 0; o >>= 1) {
        s += __shfl_down_sync(0xffffffffu, s, o);
        q += __shfl_down_sync(0xffffffffu, q, o);
    }
    int w = i >> 5, lane = i & 31;
    if (lane == 0) { red[w] = s; red[8 + w] = q; }
    __syncthreads();
    float mu  = (red[0] + red[1] + red[2] + red[3]) * (1.f / 128.f);
    float ms  = (red[8] + red[9] + red[10] + red[11]) * (1.f / 128.f);
    float var = ms - mu * mu;
    float inv = rsqrtf(var + 1e-5f);
    y[i] = (e - mu) * inv * ln_g[i] + ln_b[i];
    __syncthreads();

    if (i < 64) {
        float a = b1[i];
#pragma unroll 4
        for (int k = 0; k < 128; k++) a = fmaf(W1[i * 128 + k], y[k], a);
        hh[i] = fmaxf(a, 0.f);
    }
    __syncthreads();
    if (i < OUTW) {
        float a = b2[i];
#pragma unroll
        for (int k = 0; k < 64; k++) a = fmaf(W2[i * 64 + k], hh[k], a);
        out[b * OUTW + i] = a;
    }
}

extern "C" void kernel_launch(void* const* d_in, const int* in_sizes, int n_in,
                              void* d_out, int out_size)
{
    const float* x     = (const float*)d_in[0];
    const float* Wih00 = (const float*)d_in[1];
    const float* Whh00 = (const float*)d_in[2];
    const float* bih00 = (const float*)d_in[3];
    const float* bhh00 = (const float*)d_in[4];
    const float* Wih01 = (const float*)d_in[5];
    const float* Whh01 = (const float*)d_in[6];
    const float* bih01 = (const float*)d_in[7];
    const float* bhh01 = (const float*)d_in[8];
    const float* Wih10 = (const float*)d_in[9];
    const float* Whh10 = (const float*)d_in[10];
    const float* bih10 = (const float*)d_in[11];
    const float* bhh10 = (const float*)d_in[12];
    const float* Wih11 = (const float*)d_in[13];
    const float* Whh11 = (const float*)d_in[14];
    const float* bih11 = (const float*)d_in[15];
    const float* bhh11 = (const float*)d_in[16];
    const float* ln_g  = (const float*)d_in[17];
    const float* ln_b  = (const float*)d_in[18];
    const float* W1    = (const float*)d_in[19];
    const float* b1    = (const float*)d_in[20];
    const float* W2    = (const float*)d_in[21];
    const float* b2    = (const float*)d_in[22];

    gx0_kernel<<<dim3(TT / 64, BB, 2), 192>>>(x, Wih00, bih00, Wih01, bih01);
    recur_kernel<<<dim3(BB / 2, 2), 384>>>(Whh00, bhh00, Whh01, bhh01, 0);
    gx1_kernel<<<dim3(TT / 64, BB, 2), 384>>>(Wih10, bih10, Wih11, bih11);
    recur_kernel<<<dim3(BB / 2, 2), 384>>>(Whh10, bhh10, Whh11, bhh11, 1);
    head_kernel<<<BB, 128>>>(ln_g, ln_b, W1, b1, W2, b2, (float*)d_out);
}

// round 6
// speedup vs baseline: 1.4434x; 1.4434x over previous
#include <cuda_runtime.h>

#define BB   256
#define TT   2048
#define INW  29
#define HH   64
#define GG   192   // 3*H
#define OUTW 11

// Scratch (no cudaMalloc allowed).
__device__ float g_gx[(size_t)2 * BB * TT * GG];       // [dir][b][t][g] (natural t)
__device__ float g_out0[(size_t)BB * TT * 2 * HH];      // [b][t][128]
__device__ float g_hT[2 * BB * HH];                     // [dir][b][h]

typedef unsigned long long u64;

__device__ __forceinline__ u64 pk2(float lo, float hi) {
    u64 r; asm("mov.b64 %0,{%1,%2};" : "=l"(r) : "f"(lo), "f"(hi)); return r;
}
__device__ __forceinline__ void upk2(u64 v, float& lo, float& hi) {
    asm("mov.b64 {%0,%1},%2;" : "=f"(lo), "=f"(hi) : "l"(v));
}
// Packed fp32x2 FMA (Blackwell FFMA2) — 2x FFMA throughput vs 3-reg FFMA.
__device__ __forceinline__ u64 fma2(u64 a, u64 b, u64 c) {
    u64 d; asm("fma.rn.f32x2 %0,%1,%2,%3;" : "=l"(d) : "l"(a), "l"(b), "l"(c)); return d;
}
__device__ __forceinline__ u64 add2(u64 a, u64 b) {
    u64 d; asm("add.rn.f32x2 %0,%1,%2;" : "=l"(d) : "l"(a), "l"(b)); return d;
}
__device__ __forceinline__ float hadd2(u64 v) {
    float lo, hi; upk2(v, lo, hi); return lo + hi;
}

__device__ __forceinline__ float sigm(float x)  { return __fdividef(1.f, 1.f + __expf(-x)); }
__device__ __forceinline__ float tanh_(float x) { return __fdividef(2.f, 1.f + __expf(-2.f * x)) - 1.f; }

// ---------------------------------------------------------------------------
// Layer-0 input GEMM: gx[dir][b][t][g] = bih[g] + sum_k Wih[g][k]*x[b][t][k]
// ---------------------------------------------------------------------------
__global__ __launch_bounds__(192) void gx0_kernel(
    const float* __restrict__ x,
    const float* __restrict__ Wf, const float* __restrict__ bf,
    const float* __restrict__ Wb, const float* __restrict__ bb)
{
    int dir = blockIdx.z, b = blockIdx.y, t0 = blockIdx.x * 64;
    const float* W  = dir ? Wb : Wf;
    const float* bi = dir ? bb : bf;
    int j = threadIdx.x;

    u64 w2[INW];
#pragma unroll
    for (int k = 0; k < INW; k++) { float w = W[j * INW + k]; w2[k] = pk2(w, w); }
    float bias = bi[j];

    __shared__ __align__(16) float2 xs[INW][32];   // [k][t-pair], 64 timesteps
    for (int idx = j; idx < 64 * INW; idx += 192) {
        int tt = idx / INW, k = idx - tt * INW;
        float v = x[((size_t)b * TT + t0 + tt) * INW + k];
        ((float*)&xs[k][tt >> 1])[tt & 1] = v;
    }
    __syncthreads();

    const ulonglong2* xsq = (const ulonglong2*)xs;  // [k][16] pairs-of-pairs
    float* gxp = g_gx + ((size_t)(dir * BB + b) * TT + t0) * GG + j;
#pragma unroll 1
    for (int p2 = 0; p2 < 16; p2++) {
        u64 a0 = 0ull, a1 = 0ull;
#pragma unroll
        for (int k = 0; k < INW; k++) {
            ulonglong2 v = xsq[k * 16 + p2];
            a0 = fma2(w2[k], v.x, a0);
            a1 = fma2(w2[k], v.y, a1);
        }
        float q0, q1, q2, q3;
        upk2(a0, q0, q1); upk2(a1, q2, q3);
        gxp[(size_t)(4 * p2)     * GG] = q0 + bias;
        gxp[(size_t)(4 * p2 + 1) * GG] = q1 + bias;
        gxp[(size_t)(4 * p2 + 2) * GG] = q2 + bias;
        gxp[(size_t)(4 * p2 + 3) * GG] = q3 + bias;
    }
}

// ---------------------------------------------------------------------------
// Layer-1 input GEMM (K=128), gate-triple layout: 128 threads = 64 h-idx x
// 2 K-halves. Thread holds all 3 gate rows (j, j+64, j+128) for its K-half
// (96 packed f32x2 weight regs) -> 96 fma2 per 16 LDS.128. K-halves combined
// with one shfl_xor(16) per gate; no barriers in the t-loop.
// ---------------------------------------------------------------------------
__global__ __launch_bounds__(128, 2) void gx1_kernel(
    const float* __restrict__ Wf, const float* __restrict__ bf,
    const float* __restrict__ Wb, const float* __restrict__ bb)
{
    int dir = blockIdx.z, b = blockIdx.y, t0 = blockIdx.x * 64;
    const float* W  = dir ? Wb : Wf;
    const float* bi = dir ? bb : bf;
    int tid = threadIdx.x;
    int w = tid >> 5, l = tid & 31;
    int j  = (w << 4) | (l & 15);    // h-index 0..63
    int kh = l >> 4;                  // K-half

    u64 wr[32], wz[32], wn[32];
    {
        const u64* pr = (const u64*)(W + (size_t)(j)        * 128 + kh * 64);
        const u64* pz = (const u64*)(W + (size_t)(j + 64)   * 128 + kh * 64);
        const u64* pn = (const u64*)(W + (size_t)(j + 128)  * 128 + kh * 64);
#pragma unroll
        for (int i = 0; i < 32; i++) { wr[i] = pr[i]; wz[i] = pz[i]; wn[i] = pn[i]; }
    }
    float br = bi[j], bz = bi[j + 64], bn = bi[j + 128];

    __shared__ __align__(16) float ins[64][128];   // [t][k], 32 KB
    {
        const float4* src = (const float4*)(g_out0 + ((size_t)b * TT + t0) * 128);
        float4* dst = (float4*)ins;
        for (int idx = tid; idx < 64 * 32; idx += 128) dst[idx] = src[idx];
    }
    __syncthreads();

    float* gxp = g_gx + ((size_t)(dir * BB + b) * TT + t0) * GG + j;
#pragma unroll 1
    for (int t = 0; t < 64; t++) {
        const ulonglong2* row = (const ulonglong2*)&ins[t][kh * 64];
        u64 ar0 = 0ull, ar1 = 0ull, az0 = 0ull, az1 = 0ull, an0 = 0ull, an1 = 0ull;
#pragma unroll
        for (int i = 0; i < 16; i++) {
            ulonglong2 v = row[i];
            ar0 = fma2(wr[2 * i],     v.x, ar0);
            ar1 = fma2(wr[2 * i + 1], v.y, ar1);
            az0 = fma2(wz[2 * i],     v.x, az0);
            az1 = fma2(wz[2 * i + 1], v.y, az1);
            an0 = fma2(wn[2 * i],     v.x, an0);
            an1 = fma2(wn[2 * i + 1], v.y, an1);
        }
        float sr = hadd2(add2(ar0, ar1));
        float sz = hadd2(add2(az0, az1));
        float sn = hadd2(add2(an0, an1));
        sr += __shfl_xor_sync(0xffffffffu, sr, 16);
        sz += __shfl_xor_sync(0xffffffffu, sz, 16);
        sn += __shfl_xor_sync(0xffffffffu, sn, 16);
        if (kh == 0) {
            gxp[(size_t)t * GG]       = sr + br;
            gxp[(size_t)t * GG + 64]  = sz + bz;
            gxp[(size_t)t * GG + 128] = sn + bn;
        }
    }
}

// ---------------------------------------------------------------------------
// GRU recurrence, gate-triple layout: one CTA per (dir, batch-pair),
// 128 threads = 2 batches x 64 h-indices. Thread owns h[j] of its batch and
// all 3 gate rows for it (96 packed f32x2 weight regs); matvec reads h via
// broadcast LDS.128, full gate epilogue is thread-local (no shuffles, no
// smem gate staging). h double-buffered in smem -> ONE per-half named
// barrier per step. gx triple prefetched 2 steps deep.
// ---------------------------------------------------------------------------
__global__ __launch_bounds__(128, 2) void recur_kernel(
    const float* __restrict__ Whf, const float* __restrict__ bhf,
    const float* __restrict__ Whb, const float* __restrict__ bhb,
    int layer)
{
    int pair = blockIdx.x, dir = blockIdx.y;
    const float* W  = dir ? Whb : Whf;
    const float* bh = dir ? bhb : bhf;
    int tid = threadIdx.x;
    int bsel = tid >> 6;              // warp-uniform: warps 0-1 batch A, 2-3 batch B
    int j = tid & 63;                 // h-index
    int b = 2 * pair + bsel;

    u64 wr[32], wz[32], wn[32];
    {
        const u64* pr = (const u64*)(W + (size_t)(j)        * HH);
        const u64* pz = (const u64*)(W + (size_t)(j + 64)   * HH);
        const u64* pn = (const u64*)(W + (size_t)(j + 128)  * HH);
#pragma unroll
        for (int i = 0; i < 32; i++) { wr[i] = pr[i]; wz[i] = pz[i]; wn[i] = pn[i]; }
    }
    float br = bh[j], bz = bh[j + 64], bn = bh[j + 128];

    __shared__ __align__(16) float hbuf[2][2][HH];   // [buf][batch][h]
    hbuf[0][bsel][j] = 0.f;
    float hp = 0.f;                   // own h value (register copy)

    // gx prefetch, 2 deep; triple (r,z,n) at offsets 0/64/128 from one base.
    long stp = dir ? -(long)GG : (long)GG;
    const float* gp = g_gx + ((size_t)(dir * BB + b) * TT + (dir ? TT - 1 : 0)) * GG + j;
    float fr0 = gp[0], fz0 = gp[64], fn0 = gp[128]; gp += stp;
    float fr1 = gp[0], fz1 = gp[64], fn1 = gp[128]; gp += stp;

    float* outp = 0;
    long ostp = 0;
    if (layer == 0) {
        int tout0 = dir ? (TT - 1) : 0;
        outp = g_out0 + ((size_t)b * TT + tout0) * (2 * HH) + dir * HH + j;
        ostp = dir ? -(long)(2 * HH) : (long)(2 * HH);
    }
    __syncthreads();

    int barid = 1 + bsel;
    for (int t = 0; t < TT; t++) {
        float fr2 = 0.f, fz2 = 0.f, fn2 = 0.f;
        if (t + 2 < TT) { fr2 = gp[0]; fz2 = gp[64]; fn2 = gp[128]; gp += stp; }

        const ulonglong2* hq = (const ulonglong2*)hbuf[t & 1][bsel];
        u64 ar0 = 0ull, ar1 = 0ull, az0 = 0ull, az1 = 0ull, an0 = 0ull, an1 = 0ull;
#pragma unroll
        for (int i = 0; i < 16; i++) {
            ulonglong2 v = hq[i];
            ar0 = fma2(wr[2 * i],     v.x, ar0);
            ar1 = fma2(wr[2 * i + 1], v.y, ar1);
            az0 = fma2(wz[2 * i],     v.x, az0);
            az1 = fma2(wz[2 * i + 1], v.y, az1);
            an0 = fma2(wn[2 * i],     v.x, an0);
            an1 = fma2(wn[2 * i + 1], v.y, an1);
        }
        float r = sigm(hadd2(add2(ar0, ar1)) + br + fr0);
        float z = sigm(hadd2(add2(az0, az1)) + bz + fz0);
        float sn = hadd2(add2(an0, an1)) + bn;
        float n = tanh_(fmaf(r, sn, fn0));
        float hN = fmaf(z, hp - n, n);          // (1-z)n + z h
        hp = hN;
        hbuf[(t + 1) & 1][bsel][j] = hN;
        if (layer == 0) { *outp = hN; outp += ostp; }

        asm volatile("bar.sync %0, 64;" :: "r"(barid) : "memory");

        fr0 = fr1; fz0 = fz1; fn0 = fn1;
        fr1 = fr2; fz1 = fz2; fn1 = fn2;
    }

    if (layer == 1) g_hT[(dir * BB + b) * HH + j] = hp;
}

// ---------------------------------------------------------------------------
// Head: LayerNorm(concat(hTf, hTb)) -> ReLU(W1) -> W2. One block per batch.
// ---------------------------------------------------------------------------
__global__ __launch_bounds__(128) void head_kernel(
    const float* __restrict__ ln_g, const float* __restrict__ ln_b,
    const float* __restrict__ W1,  const float* __restrict__ b1,
    const float* __restrict__ W2,  const float* __restrict__ b2,
    float* __restrict__ out)
{
    int b = blockIdx.x, i = threadIdx.x;
    __shared__ float y[128];
    __shared__ float hh[64];
    __shared__ float red[16];

    float e = (i < 64) ? g_hT[(0 * BB + b) * HH + i]
                       : g_hT[(1 * BB + b) * HH + (i - 64)];
    float s = e, q = e * e;
#pragma unroll
    for (int o = 16; o > 0; o >>= 1) {
        s += __shfl_down_sync(0xffffffffu, s, o);
        q += __shfl_down_sync(0xffffffffu, q, o);
    }
    int w = i >> 5, lane = i & 31;
    if (lane == 0) { red[w] = s; red[8 + w] = q; }
    __syncthreads();
    float mu  = (red[0] + red[1] + red[2] + red[3]) * (1.f / 128.f);
    float ms  = (red[8] + red[9] + red[10] + red[11]) * (1.f / 128.f);
    float var = ms - mu * mu;
    float inv = rsqrtf(var + 1e-5f);
    y[i] = (e - mu) * inv * ln_g[i] + ln_b[i];
    __syncthreads();

    if (i < 64) {
        float a = b1[i];
#pragma unroll 4
        for (int k = 0; k < 128; k++) a = fmaf(W1[i * 128 + k], y[k], a);
        hh[i] = fmaxf(a, 0.f);
    }
    __syncthreads();
    if (i < OUTW) {
        float a = b2[i];
#pragma unroll
        for (int k = 0; k < 64; k++) a = fmaf(W2[i * 64 + k], hh[k], a);
        out[b * OUTW + i] = a;
    }
}

extern "C" void kernel_launch(void* const* d_in, const int* in_sizes, int n_in,
                              void* d_out, int out_size)
{
    const float* x     = (const float*)d_in[0];
    const float* Wih00 = (const float*)d_in[1];
    const float* Whh00 = (const float*)d_in[2];
    const float* bih00 = (const float*)d_in[3];
    const float* bhh00 = (const float*)d_in[4];
    const float* Wih01 = (const float*)d_in[5];
    const float* Whh01 = (const float*)d_in[6];
    const float* bih01 = (const float*)d_in[7];
    const float* bhh01 = (const float*)d_in[8];
    const float* Wih10 = (const float*)d_in[9];
    const float* Whh10 = (const float*)d_in[10];
    const float* bih10 = (const float*)d_in[11];
    const float* bhh10 = (const float*)d_in[12];
    const float* Wih11 = (const float*)d_in[13];
    const float* Whh11 = (const float*)d_in[14];
    const float* bih11 = (const float*)d_in[15];
    const float* bhh11 = (const float*)d_in[16];
    const float* ln_g  = (const float*)d_in[17];
    const float* ln_b  = (const float*)d_in[18];
    const float* W1    = (const float*)d_in[19];
    const float* b1    = (const float*)d_in[20];
    const float* W2    = (const float*)d_in[21];
    const float* b2    = (const float*)d_in[22];

    gx0_kernel<<<dim3(TT / 64, BB, 2), 192>>>(x, Wih00, bih00, Wih01, bih01);
    recur_kernel<<<dim3(BB / 2, 2), 128>>>(Whh00, bhh00, Whh01, bhh01, 0);
    gx1_kernel<<<dim3(TT / 64, BB, 2), 128>>>(Wih10, bih10, Wih11, bih11);
    recur_kernel<<<dim3(BB / 2, 2), 128>>>(Whh10, bhh10, Whh11, bhh11, 1);
    head_kernel<<<BB, 128>>>(ln_g, ln_b, W1, b1, W2, b2, (float*)d_out);
}